// round 13
// baseline (speedup 1.0000x reference)
#include <cuda_runtime.h>
#include <cstdint>
#include <cstddef>

#define TSTEPS 16384
#define BATCH  32
#define HID    96
#define GATES  384
#define NTH    416   // 12 compute warps + 1 aux (output) warp
// smem: xs0[16384] | xs1[16384] | hA0[96] hA1[96] hB0[96] hB1[96] | pad
#define SMEM_FLOATS (2 * TSTEPS + 4 * HID + 16)
#define SMEM_BYTES  (SMEM_FLOATS * sizeof(float))

__device__ __forceinline__ float tanh_fast(float x) {
    float y;
    asm("tanh.approx.f32 %0, %1;" : "=f"(y) : "f"(x));   // MUFU.TANH
    return y;
}

struct TS {
    unsigned long long w2[48];   // W_hh row as 48 packed f32x2 (shared by both elems)
    float wih, bias, c0, c1;
    float act_a, act_s, act_b;   // sigmoid = 0.5*tanh(0.5x)+0.5 ; g-gate: plain tanh
    float fw0, fw1, fw2, fcb;
    int   u;
};

// One LSTM step for BOTH batch elements of this CTA.
// Reads h_rd0/h_rd1 (h_{t-1}), quad leaders write h_wr0/h_wr1 (h_t).
__device__ __forceinline__ void lstm_step2(
    int t,
    const float* __restrict__ h_rd0, const float* __restrict__ h_rd1,
    float* __restrict__ h_wr0, float* __restrict__ h_wr1,
    const float* __restrict__ xs0, const float* __restrict__ xs1,
    float* __restrict__ out, TS& s, int tid, int b0,
    float& gx0, float& gx1)
{
    if (tid < GATES) {
        // next step's gx for both elems (independent of h; fills the window)
        const float gx0n = fmaf(xs0[t + 1], s.wih, s.bias);
        const float gx1n = fmaf(xs1[t + 1], s.wih, s.bias);

        // ---- two 96-wide dots, 4 FFMA2 chains each, gx seeded into chain 0 ----
        const ulonglong2* h0 = reinterpret_cast<const ulonglong2*>(h_rd0);
        const ulonglong2* h1 = reinterpret_cast<const ulonglong2*>(h_rd1);
        unsigned long long a0 = (unsigned long long)__float_as_uint(gx0);
        unsigned long long a1 = 0ull, a2 = 0ull, a3 = 0ull;
        unsigned long long e0 = (unsigned long long)__float_as_uint(gx1);
        unsigned long long e1 = 0ull, e2 = 0ull, e3 = 0ull;
        #pragma unroll
        for (int k = 0; k < 12; ++k) {
            ulonglong2 p = h0[2 * k];
            ulonglong2 r = h0[2 * k + 1];
            ulonglong2 q = h1[2 * k];
            ulonglong2 v = h1[2 * k + 1];
            asm("fma.rn.f32x2 %0, %1, %2, %0;" : "+l"(a0) : "l"(s.w2[4*k+0]), "l"(p.x));
            asm("fma.rn.f32x2 %0, %1, %2, %0;" : "+l"(e0) : "l"(s.w2[4*k+0]), "l"(q.x));
            asm("fma.rn.f32x2 %0, %1, %2, %0;" : "+l"(a1) : "l"(s.w2[4*k+1]), "l"(p.y));
            asm("fma.rn.f32x2 %0, %1, %2, %0;" : "+l"(e1) : "l"(s.w2[4*k+1]), "l"(q.y));
            asm("fma.rn.f32x2 %0, %1, %2, %0;" : "+l"(a2) : "l"(s.w2[4*k+2]), "l"(r.x));
            asm("fma.rn.f32x2 %0, %1, %2, %0;" : "+l"(e2) : "l"(s.w2[4*k+2]), "l"(v.x));
            asm("fma.rn.f32x2 %0, %1, %2, %0;" : "+l"(a3) : "l"(s.w2[4*k+3]), "l"(r.y));
            asm("fma.rn.f32x2 %0, %1, %2, %0;" : "+l"(e3) : "l"(s.w2[4*k+3]), "l"(v.y));
        }
        asm("add.rn.f32x2 %0, %0, %1;" : "+l"(a0) : "l"(a1));
        asm("add.rn.f32x2 %0, %0, %1;" : "+l"(a2) : "l"(a3));
        asm("add.rn.f32x2 %0, %0, %1;" : "+l"(e0) : "l"(e1));
        asm("add.rn.f32x2 %0, %0, %1;" : "+l"(e2) : "l"(e3));
        asm("add.rn.f32x2 %0, %0, %1;" : "+l"(a0) : "l"(a2));
        asm("add.rn.f32x2 %0, %0, %1;" : "+l"(e0) : "l"(e2));
        unsigned lo, hi;
        asm("mov.b64 {%0,%1}, %2;" : "=r"(lo), "=r"(hi) : "l"(a0));
        float g0 = __uint_as_float(lo) + __uint_as_float(hi);
        asm("mov.b64 {%0,%1}, %2;" : "=r"(lo), "=r"(hi) : "l"(e0));
        float g1 = __uint_as_float(lo) + __uint_as_float(hi);

        float act0 = fmaf(tanh_fast(g0 * s.act_a), s.act_s, s.act_b);
        float act1 = fmaf(tanh_fast(g1 * s.act_a), s.act_s, s.act_b);

        // ---- leader-only cell update, both elems, 3+3 quad shuffles ----
        const unsigned m = 0xffffffffu;
        float f0 = __shfl_sync(m, act0, 1, 4);
        float f1 = __shfl_sync(m, act1, 1, 4);
        float g0g = __shfl_sync(m, act0, 2, 4);
        float g1g = __shfl_sync(m, act1, 2, 4);
        float o0 = __shfl_sync(m, act0, 3, 4);
        float o1 = __shfl_sync(m, act1, 3, 4);
        if ((tid & 3) == 0) {            // leader lane: act == sigmoid(i)
            s.c0 = fmaf(f0, s.c0, act0 * g0g);
            s.c1 = fmaf(f1, s.c1, act1 * g1g);
            h_wr0[s.u] = o0 * tanh_fast(s.c0);
            h_wr1[s.u] = o1 * tanh_fast(s.c1);
        }
        gx0 = gx0n; gx1 = gx1n;
    } else if (t > 0) {
        // aux warp: outputs for step t-1, both elems (h_rd* still hold h_{t-1})
        const int l = tid - GATES;
        float p0 = s.fw0 * h_rd0[l] + s.fw1 * h_rd0[l + 32] + s.fw2 * h_rd0[l + 64];
        float p1 = s.fw0 * h_rd1[l] + s.fw1 * h_rd1[l + 32] + s.fw2 * h_rd1[l + 64];
        #pragma unroll
        for (int off = 16; off > 0; off >>= 1) {
            p0 += __shfl_xor_sync(0xffffffffu, p0, off);
            p1 += __shfl_xor_sync(0xffffffffu, p1, off);
        }
        if (l == 0) {
            out[(size_t)(t - 1) * BATCH + b0]     = p0 + s.fcb + xs0[t - 1];
            out[(size_t)(t - 1) * BATCH + b0 + 1] = p1 + s.fcb + xs1[t - 1];
        }
    }
    __syncthreads();                     // h_t published; read buffers reusable
}

__global__ void __launch_bounds__(NTH, 1)
lstm_persist2(const float* __restrict__ x,
              const float* __restrict__ w_ih,
              const float* __restrict__ w_hh,
              const float* __restrict__ b_ih,
              const float* __restrict__ b_hh,
              const float* __restrict__ fc_w,
              const float* __restrict__ fc_b,
              float* __restrict__ out)
{
    extern __shared__ float smem[];
    float* xs0 = smem;                   // [TSTEPS]
    float* xs1 = smem + TSTEPS;          // [TSTEPS]
    float* hA0 = xs1 + TSTEPS;           // [HID] elem0, buffer A
    float* hA1 = hA0 + HID;              // [HID] elem1, buffer A
    float* hB0 = hA1 + HID;              // [HID] elem0, buffer B
    float* hB1 = hB0 + HID;              // [HID] elem1, buffer B

    const int tid = threadIdx.x;
    const int b0  = blockIdx.x * 2;      // two batch elements per CTA

    // Stage both x columns into shared.
    for (int t = tid; t < TSTEPS; t += NTH) {
        xs0[t] = x[(size_t)t * BATCH + b0];
        xs1[t] = x[(size_t)t * BATCH + b0 + 1];
    }

    TS s;
    s.wih = 0.f; s.bias = 0.f; s.c0 = 0.f; s.c1 = 0.f;
    s.act_a = 0.5f; s.act_s = 0.5f; s.act_b = 0.5f;
    s.fw0 = 0.f; s.fw1 = 0.f; s.fw2 = 0.f; s.fcb = 0.f;
    s.u = 0;

    if (tid < GATES) {
        s.u = tid >> 2;                  // unit; gate q = tid&3 (0=i,1=f,2=g,3=o)
        const int q   = tid & 3;
        const int row = q * HID + s.u;
        const unsigned long long* wrow =
            reinterpret_cast<const unsigned long long*>(w_hh + row * HID);
        #pragma unroll
        for (int k = 0; k < 48; ++k) s.w2[k] = wrow[k];
        s.wih  = __ldg(w_ih + row);
        s.bias = __ldg(b_ih + row) + __ldg(b_hh + row);
        if (q == 2) { s.act_a = 1.f; s.act_s = 1.f; s.act_b = 0.f; }
    } else {
        const int l = tid - GATES;
        s.fw0 = fc_w[l]; s.fw1 = fc_w[l + 32]; s.fw2 = fc_w[l + 64];
        s.fcb = fc_b[0];
    }
    if (tid < HID) { hA0[tid] = 0.f; hA1[tid] = 0.f; }   // h0 = 0; c0 in regs
    __syncthreads();

    float gx0 = (tid < GATES) ? fmaf(xs0[0], s.wih, s.bias) : 0.f;
    float gx1 = (tid < GATES) ? fmaf(xs1[0], s.wih, s.bias) : 0.f;

    // 2x-unrolled: even step A->B, odd step B->A.
    #pragma unroll 1
    for (int t = 0; t < TSTEPS; t += 2) {
        lstm_step2(t,     hA0, hA1, hB0, hB1, xs0, xs1, out, s, tid, b0, gx0, gx1);
        lstm_step2(t + 1, hB0, hB1, hA0, hA1, xs0, xs1, out, s, tid, b0, gx0, gx1);
    }
    // (last gx reads xs0[TSTEPS]==xs1[0] and xs1[TSTEPS]==hA0[0]: in-bounds, unused)

    // Final outputs for t = TSTEPS-1 (odd step wrote into A buffers).
    if (tid >= GATES) {
        const int l = tid - GATES;
        float p0 = s.fw0 * hA0[l] + s.fw1 * hA0[l + 32] + s.fw2 * hA0[l + 64];
        float p1 = s.fw0 * hA1[l] + s.fw1 * hA1[l + 32] + s.fw2 * hA1[l + 64];
        #pragma unroll
        for (int off = 16; off > 0; off >>= 1) {
            p0 += __shfl_xor_sync(0xffffffffu, p0, off);
            p1 += __shfl_xor_sync(0xffffffffu, p1, off);
        }
        if (l == 0) {
            out[(size_t)(TSTEPS - 1) * BATCH + b0]     = p0 + s.fcb + xs0[TSTEPS - 1];
            out[(size_t)(TSTEPS - 1) * BATCH + b0 + 1] = p1 + s.fcb + xs1[TSTEPS - 1];
        }
    }
}

extern "C" void kernel_launch(void* const* d_in, const int* in_sizes, int n_in,
                              void* d_out, int out_size)
{
    const float* x    = (const float*)d_in[0];
    const float* w_ih = (const float*)d_in[1];
    const float* w_hh = (const float*)d_in[2];
    const float* b_ih = (const float*)d_in[3];
    const float* b_hh = (const float*)d_in[4];
    const float* fc_w = (const float*)d_in[5];
    const float* fc_b = (const float*)d_in[6];
    float* out = (float*)d_out;

    cudaFuncSetAttribute(lstm_persist2,
                         cudaFuncAttributeMaxDynamicSharedMemorySize,
                         (int)SMEM_BYTES);
    lstm_persist2<<<BATCH / 2, NTH, SMEM_BYTES>>>(x, w_ih, w_hh, b_ih, b_hh,
                                                  fc_w, fc_b, out);
}

// round 14
// speedup vs baseline: 1.9474x; 1.9474x over previous
#include <cuda_runtime.h>
#include <cstdint>
#include <cstddef>

#define TSTEPS 16384
#define BATCH  32
#define HID    96
#define GATES  384
#define NTH    416   // 12 compute warps + 1 aux (output) warp
// pad generously: prefetch may read up to 32B past the h buffers
#define SMEM_FLOATS (TSTEPS + 2 * HID + 32)
#define SMEM_BYTES  (SMEM_FLOATS * sizeof(float))

__device__ __forceinline__ float tanh_fast(float x) {
    float y;
    asm("tanh.approx.f32 %0, %1;" : "=f"(y) : "f"(x));   // MUFU.TANH
    return y;
}

struct TS {
    unsigned long long w2[48];   // W_hh row as 48 packed f32x2
    float wih, bias, c;
    float act_a, act_s, act_b;   // sigmoid = 0.5*tanh(0.5x)+0.5 ; g-gate: plain tanh
    float fw0, fw1, fw2, fcb;
    int   u;
};

// One LSTM step. h_rd: h_{t-1}; quad leaders write h_wr[u] = h_t.
// Matvec loads are explicitly software-pipelined 2 iterations deep.
__device__ __forceinline__ float lstm_step(
    int t, const float* __restrict__ h_rd, float* __restrict__ h_wr,
    const float* __restrict__ xs, float* __restrict__ out,
    TS& s, int tid, int b, float gx_cur)
{
    float gx_next = 0.f;
    if (tid < GATES) {
        gx_next = fmaf(xs[t + 1], s.wih, s.bias);   // next step's gx, off the tail

        const ulonglong2* hv = reinterpret_cast<const ulonglong2*>(h_rd);
        unsigned long long a0 = (unsigned long long)__float_as_uint(gx_cur);
        unsigned long long a1 = 0ull, a2 = 0ull, a3 = 0ull;

        // depth-2 rolling prefetch: iter k consumes (p0,p1), (q,r) hold k+1/k+2
        ulonglong2 p0 = hv[0], p1 = hv[1];
        ulonglong2 q0 = hv[2], q1 = hv[3];
        #pragma unroll
        for (int k = 0; k < 12; ++k) {
            ulonglong2 r0, r1;
            if (k < 10) { r0 = hv[2 * k + 4]; r1 = hv[2 * k + 5]; }
            else        { r0 = p0;            r1 = p1; }          // dead values
            asm("fma.rn.f32x2 %0, %1, %2, %0;" : "+l"(a0) : "l"(s.w2[4*k+0]), "l"(p0.x));
            asm("fma.rn.f32x2 %0, %1, %2, %0;" : "+l"(a1) : "l"(s.w2[4*k+1]), "l"(p0.y));
            asm("fma.rn.f32x2 %0, %1, %2, %0;" : "+l"(a2) : "l"(s.w2[4*k+2]), "l"(p1.x));
            asm("fma.rn.f32x2 %0, %1, %2, %0;" : "+l"(a3) : "l"(s.w2[4*k+3]), "l"(p1.y));
            p0 = q0; p1 = q1; q0 = r0; q1 = r1;   // SSA-renamed under full unroll
        }
        asm("add.rn.f32x2 %0, %0, %1;" : "+l"(a0) : "l"(a1));
        asm("add.rn.f32x2 %0, %0, %1;" : "+l"(a2) : "l"(a3));
        asm("add.rn.f32x2 %0, %0, %1;" : "+l"(a0) : "l"(a2));
        unsigned lo, hi;
        asm("mov.b64 {%0,%1}, %2;" : "=r"(lo), "=r"(hi) : "l"(a0));
        float g   = __uint_as_float(lo) + __uint_as_float(hi);
        float act = fmaf(tanh_fast(g * s.act_a), s.act_s, s.act_b);

        // leader-only cell update: gather f,g,o with 3 quad shuffles
        const unsigned m = 0xffffffffu;
        float vf = __shfl_sync(m, act, 1, 4);
        float vg = __shfl_sync(m, act, 2, 4);
        float vo = __shfl_sync(m, act, 3, 4);
        if ((tid & 3) == 0) {              // leader lane: act == sigmoid(i)
            s.c = fmaf(vf, s.c, act * vg);
            h_wr[s.u] = vo * tanh_fast(s.c);
        }
    } else if (t > 0) {
        // aux warp: out[t-1] = fc_w . h_{t-1} + fc_b + x[t-1]
        const int l = tid - GATES;
        float p = s.fw0 * h_rd[l] + s.fw1 * h_rd[l + 32] + s.fw2 * h_rd[l + 64];
        #pragma unroll
        for (int off = 16; off > 0; off >>= 1)
            p += __shfl_xor_sync(0xffffffffu, p, off);
        if (l == 0)
            out[(size_t)(t - 1) * BATCH + b] = p + s.fcb + xs[t - 1];
    }
    __syncthreads();                       // h_t published; h_rd reusable
    return gx_next;
}

__global__ void __launch_bounds__(NTH, 1)
lstm_persist(const float* __restrict__ x,
             const float* __restrict__ w_ih,
             const float* __restrict__ w_hh,
             const float* __restrict__ b_ih,
             const float* __restrict__ b_hh,
             const float* __restrict__ fc_w,
             const float* __restrict__ fc_b,
             float* __restrict__ out)
{
    extern __shared__ float smem[];
    float* xs  = smem;                   // [TSTEPS]
    float* hb0 = smem + TSTEPS;          // [HID] buffer A
    float* hb1 = hb0 + HID;              // [HID] buffer B (pad after for prefetch)

    const int tid = threadIdx.x;
    const int b   = blockIdx.x;          // one CTA / batch element / SM

    for (int t = tid; t < TSTEPS; t += NTH)
        xs[t] = x[(size_t)t * BATCH + b];

    TS s;
    s.wih = 0.f; s.bias = 0.f; s.c = 0.f;
    s.act_a = 0.5f; s.act_s = 0.5f; s.act_b = 0.5f;
    s.fw0 = 0.f; s.fw1 = 0.f; s.fw2 = 0.f; s.fcb = 0.f;
    s.u = 0;

    if (tid < GATES) {
        s.u = tid >> 2;                  // unit; gate q = tid&3 (0=i,1=f,2=g,3=o)
        const int q   = tid & 3;
        const int row = q * HID + s.u;
        const unsigned long long* wrow =
            reinterpret_cast<const unsigned long long*>(w_hh + row * HID);
        #pragma unroll
        for (int k = 0; k < 48; ++k) s.w2[k] = wrow[k];
        s.wih  = __ldg(w_ih + row);
        s.bias = __ldg(b_ih + row) + __ldg(b_hh + row);
        if (q == 2) { s.act_a = 1.f; s.act_s = 1.f; s.act_b = 0.f; }
    } else {
        const int l = tid - GATES;       // aux warp: fc weights, 3 per lane
        s.fw0 = fc_w[l]; s.fw1 = fc_w[l + 32]; s.fw2 = fc_w[l + 64];
        s.fcb = fc_b[0];
    }
    if (tid < HID) hb0[tid] = 0.f;       // h0 = 0; c0 = 0 in regs
    __syncthreads();

    float gx = (tid < GATES) ? fmaf(xs[0], s.wih, s.bias) : 0.f;

    // 2x-unrolled: even step A->B, odd step B->A (no pointer-swap ALU).
    #pragma unroll 1
    for (int t = 0; t < TSTEPS; t += 2) {
        gx = lstm_step(t,     hb0, hb1, xs, out, s, tid, b, gx);
        gx = lstm_step(t + 1, hb1, hb0, xs, out, s, tid, b, gx);
    }
    // (last gx reads xs[TSTEPS] == hb0[0]: in-bounds smem, value unused)

    // Final output for t = TSTEPS-1 (odd step wrote into hb0).
    if (tid >= GATES) {
        const int l = tid - GATES;
        float p = s.fw0 * hb0[l] + s.fw1 * hb0[l + 32] + s.fw2 * hb0[l + 64];
        #pragma unroll
        for (int off = 16; off > 0; off >>= 1)
            p += __shfl_xor_sync(0xffffffffu, p, off);
        if (l == 0)
            out[(size_t)(TSTEPS - 1) * BATCH + b] = p + s.fcb + xs[TSTEPS - 1];
    }
}

extern "C" void kernel_launch(void* const* d_in, const int* in_sizes, int n_in,
                              void* d_out, int out_size)
{
    const float* x    = (const float*)d_in[0];
    const float* w_ih = (const float*)d_in[1];
    const float* w_hh = (const float*)d_in[2];
    const float* b_ih = (const float*)d_in[3];
    const float* b_hh = (const float*)d_in[4];
    const float* fc_w = (const float*)d_in[5];
    const float* fc_b = (const float*)d_in[6];
    float* out = (float*)d_out;

    cudaFuncSetAttribute(lstm_persist,
                         cudaFuncAttributeMaxDynamicSharedMemorySize,
                         (int)SMEM_BYTES);
    lstm_persist<<<BATCH, NTH, SMEM_BYTES>>>(x, w_ih, w_hh, b_ih, b_hh,
                                             fc_w, fc_b, out);
}

// round 15
// speedup vs baseline: 2.0086x; 1.0314x over previous
#include <cuda_runtime.h>
#include <cstdint>
#include <cstddef>

#define TSTEPS 16384
#define BATCH  32
#define HID    96
#define GATES  384
#define NTH    416   // 12 compute warps + 1 aux (output) warp
#define SMEM_FLOATS (TSTEPS + 2 * HID + 32)
#define SMEM_BYTES  (SMEM_FLOATS * sizeof(float))

__device__ __forceinline__ float tanh_fast(float x) {
    float y;
    asm("tanh.approx.f32 %0, %1;" : "=f"(y) : "f"(x));   // MUFU.TANH
    return y;
}

struct TS {
    float w[96];                 // W_hh row, scalar fp32 (FFMA rt=2 vs FFMA2 rt~6)
    float wih, bias, c;
    float act_a, act_s, act_b;   // sigmoid = 0.5*tanh(0.5x)+0.5 ; g-gate: plain tanh
    float fw0, fw1, fw2, fcb;
    int   u;
};

// One LSTM step. h_rd: h_{t-1}; quad leaders write h_wr[u] = h_t.
__device__ __forceinline__ float lstm_step(
    int t, const float* __restrict__ h_rd, float* __restrict__ h_wr,
    const float* __restrict__ xs, float* __restrict__ out,
    TS& s, int tid, int b, float gx_cur)
{
    float gx_next = 0.f;
    if (tid < GATES) {
        gx_next = fmaf(xs[t + 1], s.wih, s.bias);   // next step's gx, off the tail

        // ---- 96-wide dot as SCALAR FFMA, 4 independent chains of 24 ----
        const float4* hv = reinterpret_cast<const float4*>(h_rd);
        float a0 = gx_cur, a1 = 0.f, a2 = 0.f, a3 = 0.f;
        #pragma unroll
        for (int k = 0; k < 24; ++k) {
            float4 h4 = hv[k];                      // LDS.128 broadcast
            a0 = fmaf(s.w[4 * k + 0], h4.x, a0);
            a1 = fmaf(s.w[4 * k + 1], h4.y, a1);
            a2 = fmaf(s.w[4 * k + 2], h4.z, a2);
            a3 = fmaf(s.w[4 * k + 3], h4.w, a3);
        }
        float g   = (a0 + a1) + (a2 + a3);
        float act = fmaf(tanh_fast(g * s.act_a), s.act_s, s.act_b);

        // ---- leader-only cell update: gather f,g,o with 3 quad shuffles ----
        const unsigned m = 0xffffffffu;
        float vf = __shfl_sync(m, act, 1, 4);
        float vg = __shfl_sync(m, act, 2, 4);
        float vo = __shfl_sync(m, act, 3, 4);
        if ((tid & 3) == 0) {              // leader lane: act == sigmoid(i)
            s.c = fmaf(vf, s.c, act * vg);
            h_wr[s.u] = vo * tanh_fast(s.c);
        }
    } else if (t > 0) {
        // aux warp: out[t-1] = fc_w . h_{t-1} + fc_b + x[t-1]
        const int l = tid - GATES;
        float p = s.fw0 * h_rd[l] + s.fw1 * h_rd[l + 32] + s.fw2 * h_rd[l + 64];
        #pragma unroll
        for (int off = 16; off > 0; off >>= 1)
            p += __shfl_xor_sync(0xffffffffu, p, off);
        if (l == 0)
            out[(size_t)(t - 1) * BATCH + b] = p + s.fcb + xs[t - 1];
    }
    __syncthreads();                       // h_t published; h_rd reusable
    return gx_next;
}

__global__ void __launch_bounds__(NTH, 1)
lstm_persist(const float* __restrict__ x,
             const float* __restrict__ w_ih,
             const float* __restrict__ w_hh,
             const float* __restrict__ b_ih,
             const float* __restrict__ b_hh,
             const float* __restrict__ fc_w,
             const float* __restrict__ fc_b,
             float* __restrict__ out)
{
    extern __shared__ float smem[];
    float* xs  = smem;                   // [TSTEPS]
    float* hb0 = smem + TSTEPS;          // [HID] buffer A (16B-aligned)
    float* hb1 = hb0 + HID;              // [HID] buffer B

    const int tid = threadIdx.x;
    const int b   = blockIdx.x;          // one CTA / batch element / SM

    for (int t = tid; t < TSTEPS; t += NTH)
        xs[t] = x[(size_t)t * BATCH + b];

    TS s;
    s.wih = 0.f; s.bias = 0.f; s.c = 0.f;
    s.act_a = 0.5f; s.act_s = 0.5f; s.act_b = 0.5f;
    s.fw0 = 0.f; s.fw1 = 0.f; s.fw2 = 0.f; s.fcb = 0.f;
    s.u = 0;

    if (tid < GATES) {
        s.u = tid >> 2;                  // unit; gate q = tid&3 (0=i,1=f,2=g,3=o)
        const int q   = tid & 3;
        const int row = q * HID + s.u;
        const float4* wrow = reinterpret_cast<const float4*>(w_hh + row * HID);
        #pragma unroll
        for (int k = 0; k < 24; ++k) {
            float4 w4 = wrow[k];
            s.w[4 * k + 0] = w4.x; s.w[4 * k + 1] = w4.y;
            s.w[4 * k + 2] = w4.z; s.w[4 * k + 3] = w4.w;
        }
        s.wih  = __ldg(w_ih + row);
        s.bias = __ldg(b_ih + row) + __ldg(b_hh + row);
        if (q == 2) { s.act_a = 1.f; s.act_s = 1.f; s.act_b = 0.f; }
    } else {
        const int l = tid - GATES;       // aux warp: fc weights, 3 per lane
        s.fw0 = fc_w[l]; s.fw1 = fc_w[l + 32]; s.fw2 = fc_w[l + 64];
        s.fcb = fc_b[0];
    }
    if (tid < HID) hb0[tid] = 0.f;       // h0 = 0; c0 = 0 in regs
    __syncthreads();

    float gx = (tid < GATES) ? fmaf(xs[0], s.wih, s.bias) : 0.f;

    // 2x-unrolled: even step A->B, odd step B->A (no pointer-swap ALU).
    #pragma unroll 1
    for (int t = 0; t < TSTEPS; t += 2) {
        gx = lstm_step(t,     hb0, hb1, xs, out, s, tid, b, gx);
        gx = lstm_step(t + 1, hb1, hb0, xs, out, s, tid, b, gx);
    }
    // (last gx reads xs[TSTEPS] == hb0[0]: in-bounds smem, value unused)

    // Final output for t = TSTEPS-1 (odd step wrote into hb0).
    if (tid >= GATES) {
        const int l = tid - GATES;
        float p = s.fw0 * hb0[l] + s.fw1 * hb0[l + 32] + s.fw2 * hb0[l + 64];
        #pragma unroll
        for (int off = 16; off > 0; off >>= 1)
            p += __shfl_xor_sync(0xffffffffu, p, off);
        if (l == 0)
            out[(size_t)(TSTEPS - 1) * BATCH + b] = p + s.fcb + xs[TSTEPS - 1];
    }
}

extern "C" void kernel_launch(void* const* d_in, const int* in_sizes, int n_in,
                              void* d_out, int out_size)
{
    const float* x    = (const float*)d_in[0];
    const float* w_ih = (const float*)d_in[1];
    const float* w_hh = (const float*)d_in[2];
    const float* b_ih = (const float*)d_in[3];
    const float* b_hh = (const float*)d_in[4];
    const float* fc_w = (const float*)d_in[5];
    const float* fc_b = (const float*)d_in[6];
    float* out = (float*)d_out;

    cudaFuncSetAttribute(lstm_persist,
                         cudaFuncAttributeMaxDynamicSharedMemorySize,
                         (int)SMEM_BYTES);
    lstm_persist<<<BATCH, NTH, SMEM_BYTES>>>(x, w_ih, w_hh, b_ih, b_hh,
                                             fc_w, fc_b, out);
}

// round 16
// speedup vs baseline: 2.3723x; 1.1811x over previous
#include <cuda_runtime.h>
#include <cuda_fp16.h>
#include <cstdint>
#include <cstddef>

#define TSTEPS 16384
#define BATCH  32
#define HID    96
#define GATES  384
#define NTH    416   // 12 compute warps + 1 aux (output) warp
// smem: xs[16384] fp32 | hb0[96] half | hb1[96] half | pad  (each h buf 192B, 16B-aligned)
#define SMEM_FLOATS (TSTEPS + 2 * 48 + 32)
#define SMEM_BYTES  (SMEM_FLOATS * sizeof(float))

__device__ __forceinline__ float tanh_fast(float x) {
    float y;
    asm("tanh.approx.f32 %0, %1;" : "=f"(y) : "f"(x));   // MUFU.TANH
    return y;
}

struct TS {
    __half2 w2[48];              // W_hh row as 48 fp16x2 (HFMA2: 1 slot = 2 MACs)
    float wih, bias, c;
    float act_a, act_s, act_b;   // sigmoid = 0.5*tanh(0.5x)+0.5 ; g-gate: plain tanh
    float fw0, fw1, fw2, fcb;
    int   u;
};

// One LSTM step. h_rd: h_{t-1} (fp16); quad leaders write h_wr[u] = h_t (fp16).
__device__ __forceinline__ float lstm_step(
    int t, const __half* __restrict__ h_rd, __half* __restrict__ h_wr,
    const float* __restrict__ xs, float* __restrict__ out,
    TS& s, int tid, int b, float gx_cur)
{
    float gx_next = 0.f;
    if (tid < GATES) {
        gx_next = fmaf(xs[t + 1], s.wih, s.bias);   // next step's gx, off the tail

        // ---- 96-wide dot as 48 HFMA2, 8 independent fp16x2 chains ----
        const uint4* hv = reinterpret_cast<const uint4*>(h_rd);  // 12 x 16B = 96 halves
        __half2 acc[8];
        #pragma unroll
        for (int j = 0; j < 8; ++j) acc[j] = __float2half2_rn(0.f);
        #pragma unroll
        for (int k = 0; k < 12; ++k) {
            uint4 v = hv[k];                        // LDS.128 broadcast: 8 half2
            __half2 h0 = *reinterpret_cast<__half2*>(&v.x);
            __half2 h1 = *reinterpret_cast<__half2*>(&v.y);
            __half2 h2 = *reinterpret_cast<__half2*>(&v.z);
            __half2 h3 = *reinterpret_cast<__half2*>(&v.w);
            const int c0 = (k & 1) * 4;             // alternate chain groups 0-3 / 4-7
            acc[c0 + 0] = __hfma2(s.w2[4 * k + 0], h0, acc[c0 + 0]);
            acc[c0 + 1] = __hfma2(s.w2[4 * k + 1], h1, acc[c0 + 1]);
            acc[c0 + 2] = __hfma2(s.w2[4 * k + 2], h2, acc[c0 + 2]);
            acc[c0 + 3] = __hfma2(s.w2[4 * k + 3], h3, acc[c0 + 3]);
        }
        // fp32 finish: convert each chain, tree-sum (avoids large-magnitude fp16 rounds)
        float2 f0 = __half22float2(acc[0]), f1 = __half22float2(acc[1]);
        float2 f2 = __half22float2(acc[2]), f3 = __half22float2(acc[3]);
        float2 f4 = __half22float2(acc[4]), f5 = __half22float2(acc[5]);
        float2 f6 = __half22float2(acc[6]), f7 = __half22float2(acc[7]);
        float s01 = (f0.x + f0.y) + (f1.x + f1.y);
        float s23 = (f2.x + f2.y) + (f3.x + f3.y);
        float s45 = (f4.x + f4.y) + (f5.x + f5.y);
        float s67 = (f6.x + f6.y) + (f7.x + f7.y);
        float g   = ((s01 + s23) + (s45 + s67)) + gx_cur;
        float act = fmaf(tanh_fast(g * s.act_a), s.act_s, s.act_b);

        // ---- leader-only cell update: gather f,g,o with 3 quad shuffles ----
        const unsigned m = 0xffffffffu;
        float vf = __shfl_sync(m, act, 1, 4);
        float vg = __shfl_sync(m, act, 2, 4);
        float vo = __shfl_sync(m, act, 3, 4);
        if ((tid & 3) == 0) {              // leader lane: act == sigmoid(i)
            s.c = fmaf(vf, s.c, act * vg); // c stays fp32 (long-term memory)
            h_wr[s.u] = __float2half_rn(vo * tanh_fast(s.c));
        }
    } else if (t > 0) {
        // aux warp: out[t-1] = fc_w . h_{t-1} + fc_b + x[t-1]
        const int l = tid - GATES;
        float p = s.fw0 * __half2float(h_rd[l])
                + s.fw1 * __half2float(h_rd[l + 32])
                + s.fw2 * __half2float(h_rd[l + 64]);
        #pragma unroll
        for (int off = 16; off > 0; off >>= 1)
            p += __shfl_xor_sync(0xffffffffu, p, off);
        if (l == 0)
            out[(size_t)(t - 1) * BATCH + b] = p + s.fcb + xs[t - 1];
    }
    __syncthreads();                       // h_t published; h_rd reusable
    return gx_next;
}

__global__ void __launch_bounds__(NTH, 1)
lstm_persist(const float* __restrict__ x,
             const float* __restrict__ w_ih,
             const float* __restrict__ w_hh,
             const float* __restrict__ b_ih,
             const float* __restrict__ b_hh,
             const float* __restrict__ fc_w,
             const float* __restrict__ fc_b,
             float* __restrict__ out)
{
    extern __shared__ float smem[];
    float*  xs  = smem;                              // [TSTEPS]
    __half* hb0 = reinterpret_cast<__half*>(smem + TSTEPS);        // [96] (192B)
    __half* hb1 = hb0 + HID;                                        // [96]

    const int tid = threadIdx.x;
    const int b   = blockIdx.x;          // one CTA / batch element / SM

    for (int t = tid; t < TSTEPS; t += NTH)
        xs[t] = x[(size_t)t * BATCH + b];

    TS s;
    s.wih = 0.f; s.bias = 0.f; s.c = 0.f;
    s.act_a = 0.5f; s.act_s = 0.5f; s.act_b = 0.5f;
    s.fw0 = 0.f; s.fw1 = 0.f; s.fw2 = 0.f; s.fcb = 0.f;
    s.u = 0;

    if (tid < GATES) {
        s.u = tid >> 2;                  // unit; gate q = tid&3 (0=i,1=f,2=g,3=o)
        const int q   = tid & 3;
        const int row = q * HID + s.u;
        const float2* wrow = reinterpret_cast<const float2*>(w_hh + row * HID);
        #pragma unroll
        for (int k = 0; k < 48; ++k) {
            float2 w = wrow[k];
            s.w2[k] = __floats2half2_rn(w.x, w.y);
        }
        s.wih  = __ldg(w_ih + row);
        s.bias = __ldg(b_ih + row) + __ldg(b_hh + row);
        if (q == 2) { s.act_a = 1.f; s.act_s = 1.f; s.act_b = 0.f; }
    } else {
        const int l = tid - GATES;       // aux warp: fc weights, 3 per lane
        s.fw0 = fc_w[l]; s.fw1 = fc_w[l + 32]; s.fw2 = fc_w[l + 64];
        s.fcb = fc_b[0];
    }
    if (tid < HID) hb0[tid] = __float2half_rn(0.f);  // h0 = 0; c0 = 0 in regs
    __syncthreads();

    float gx = (tid < GATES) ? fmaf(xs[0], s.wih, s.bias) : 0.f;

    // 2x-unrolled: even step hb0->hb1, odd step hb1->hb0.
    #pragma unroll 1
    for (int t = 0; t < TSTEPS; t += 2) {
        gx = lstm_step(t,     hb0, hb1, xs, out, s, tid, b, gx);
        gx = lstm_step(t + 1, hb1, hb0, xs, out, s, tid, b, gx);
    }
    // (last gx reads xs[TSTEPS] == start of hb0: in-bounds smem bits, value unused)

    // Final output for t = TSTEPS-1 (odd step wrote into hb0).
    if (tid >= GATES) {
        const int l = tid - GATES;
        float p = s.fw0 * __half2float(hb0[l])
                + s.fw1 * __half2float(hb0[l + 32])
                + s.fw2 * __half2float(hb0[l + 64]);
        #pragma unroll
        for (int off = 16; off > 0; off >>= 1)
            p += __shfl_xor_sync(0xffffffffu, p, off);
        if (l == 0)
            out[(size_t)(TSTEPS - 1) * BATCH + b] = p + s.fcb + xs[TSTEPS - 1];
    }
}

extern "C" void kernel_launch(void* const* d_in, const int* in_sizes, int n_in,
                              void* d_out, int out_size)
{
    const float* x    = (const float*)d_in[0];
    const float* w_ih = (const float*)d_in[1];
    const float* w_hh = (const float*)d_in[2];
    const float* b_ih = (const float*)d_in[3];
    const float* b_hh = (const float*)d_in[4];
    const float* fc_w = (const float*)d_in[5];
    const float* fc_b = (const float*)d_in[6];
    float* out = (float*)d_out;

    cudaFuncSetAttribute(lstm_persist,
                         cudaFuncAttributeMaxDynamicSharedMemorySize,
                         (int)SMEM_BYTES);
    lstm_persist<<<BATCH, NTH, SMEM_BYTES>>>(x, w_ih, w_hh, b_ih, b_hh,
                                             fc_w, fc_b, out);
}

// round 17
// speedup vs baseline: 3.0160x; 1.2713x over previous
#include <cuda_runtime.h>
#include <cuda_fp16.h>
#include <cstdint>
#include <cstddef>

#define TSTEPS 16384
#define BATCH  32
#define HID    96
#define NTH    416   // 12 compute warps + 1 aux (output) warp
// smem: xs[16384] fp32 | hb0[96] half | hb1[96] half | pad
#define SMEM_FLOATS (TSTEPS + 2 * 48 + 32)
#define SMEM_BYTES  (SMEM_FLOATS * sizeof(float))

__device__ __forceinline__ float tanh_fast(float x) {
    float y;
    asm("tanh.approx.f32 %0, %1;" : "=f"(y) : "f"(x));   // MUFU.TANH
    return y;
}
__device__ __forceinline__ float sigm_fast(float x) {   // 0.5*tanh(0.5x)+0.5
    return fmaf(tanh_fast(0.5f * x), 0.5f, 0.5f);
}

// D(m16n8,f32) += A(m16k16,f16 row) * B(k16n8,f16 col); B cols all equal -> D cols equal.
__device__ __forceinline__ void mma_16816(
    float& d0, float& d1, float& d2, float& d3,
    const uint32_t* a, uint32_t b0, uint32_t b1)
{
    asm volatile(
        "mma.sync.aligned.m16n8k16.row.col.f32.f16.f16.f32 "
        "{%0,%1,%2,%3}, {%4,%5,%6,%7}, {%8,%9}, {%0,%1,%2,%3};"
        : "+f"(d0), "+f"(d1), "+f"(d2), "+f"(d3)
        : "r"(a[0]), "r"(a[1]), "r"(a[2]), "r"(a[3]), "r"(b0), "r"(b1));
}

struct TS {
    uint32_t A[2][6][4];         // A fragments: tile{0:i/f,1:g/o} x 6 k-tiles x 4 .f16x2
    float wih4[4], bias4[4], c;  // per-gate gx params (i,f,g,o); cell state
    float fw0, fw1, fw2, fcb;    // aux warp fc params
    int   unit;
};

// One LSTM step. h_rd: h_{t-1} (fp16); lane%4==0 writes h_wr[unit] = h_t.
__device__ __forceinline__ void lstm_step(
    int t, const __half* __restrict__ h_rd, __half* __restrict__ h_wr,
    const float* __restrict__ xs, float* __restrict__ out,
    TS& s, int w, int lane, int b)
{
    if (w < 12) {
        const float xt = xs[t];
        // seed accumulators with gx = x_t*w_ih + (b_ih+b_hh) per gate row
        float d0 = fmaf(xt, s.wih4[0], s.bias4[0]);   // gate i (tile0 row gr)
        float d1 = 0.f;
        float d2 = fmaf(xt, s.wih4[1], s.bias4[1]);   // gate f (tile0 row gr+8)
        float d3 = 0.f;
        float e0 = fmaf(xt, s.wih4[2], s.bias4[2]);   // gate g (tile1 row gr)
        float e1 = 0.f;
        float e2 = fmaf(xt, s.wih4[3], s.bias4[3]);   // gate o (tile1 row gr+8)
        float e3 = 0.f;

        // B fragments: b0 = h[16kt + 2*tig .. +1], b1 = h[16kt+8+2*tig .. +1]
        const int tig = lane & 3;
        const char* hp = reinterpret_cast<const char*>(h_rd) + 4 * tig;
        #pragma unroll
        for (int kt = 0; kt < 6; ++kt) {
            uint32_t b0 = *reinterpret_cast<const uint32_t*>(hp + 32 * kt);
            uint32_t b1 = *reinterpret_cast<const uint32_t*>(hp + 32 * kt + 16);
            mma_16816(d0, d1, d2, d3, s.A[0][kt], b0, b1);
            mma_16816(e0, e1, e2, e3, s.A[1][kt], b0, b1);
        }

        // all 4 gates of this thread's unit are in-thread: no shuffles
        float gi = sigm_fast(d0);
        float gf = sigm_fast(d2);
        float gg = tanh_fast(e0);
        float go = sigm_fast(e2);
        s.c = fmaf(gf, s.c, gi * gg);                 // c fp32 (replicated x4 lanes)
        float h = go * tanh_fast(s.c);
        if ((lane & 3) == 0) h_wr[s.unit] = __float2half_rn(h);
    } else if (t > 0) {
        // aux warp: out[t-1] = fc_w . h_{t-1} + fc_b + x[t-1]
        float p = s.fw0 * __half2float(h_rd[lane])
                + s.fw1 * __half2float(h_rd[lane + 32])
                + s.fw2 * __half2float(h_rd[lane + 64]);
        #pragma unroll
        for (int off = 16; off > 0; off >>= 1)
            p += __shfl_xor_sync(0xffffffffu, p, off);
        if (lane == 0)
            out[(size_t)(t - 1) * BATCH + b] = p + s.fcb + xs[t - 1];
    }
    __syncthreads();                       // h_t published; h_rd reusable
}

__global__ void __launch_bounds__(NTH, 1)
lstm_mma(const float* __restrict__ x,
         const float* __restrict__ w_ih,
         const float* __restrict__ w_hh,
         const float* __restrict__ b_ih,
         const float* __restrict__ b_hh,
         const float* __restrict__ fc_w,
         const float* __restrict__ fc_b,
         float* __restrict__ out)
{
    extern __shared__ float smem[];
    float*  xs  = smem;                                       // [TSTEPS]
    __half* hb0 = reinterpret_cast<__half*>(smem + TSTEPS);   // [96]
    __half* hb1 = hb0 + HID;                                  // [96]

    const int tid  = threadIdx.x;
    const int b    = blockIdx.x;          // one CTA / batch element / SM
    const int w    = tid >> 5;
    const int lane = tid & 31;
    const int gr   = lane >> 2;           // fragment row group 0..7
    const int tig  = lane & 3;            // thread-in-group (k/col offset)

    for (int t = tid; t < TSTEPS; t += NTH)
        xs[t] = x[(size_t)t * BATCH + b];

    TS s;
    s.c = 0.f; s.unit = 0;
    s.fw0 = 0.f; s.fw1 = 0.f; s.fw2 = 0.f; s.fcb = 0.f;
    #pragma unroll
    for (int q = 0; q < 4; ++q) { s.wih4[q] = 0.f; s.bias4[q] = 0.f; }

    if (w < 12) {
        // warp w owns units [8w, 8w+8); thread's unit = 8w + gr.
        // tile0 rows: gr -> gate i, gr+8 -> gate f ; tile1: gr -> g, gr+8 -> o.
        s.unit = 8 * w + gr;
        int rows[4];
        #pragma unroll
        for (int q = 0; q < 4; ++q) {
            rows[q]    = q * HID + s.unit;        // W_hh row for gate q
            s.wih4[q]  = __ldg(w_ih + rows[q]);
            s.bias4[q] = __ldg(b_ih + rows[q]) + __ldg(b_hh + rows[q]);
        }
        #pragma unroll
        for (int t2 = 0; t2 < 2; ++t2) {
            const float* r0 = w_hh + rows[2 * t2] * HID;       // row gr
            const float* r1 = w_hh + rows[2 * t2 + 1] * HID;   // row gr+8
            #pragma unroll
            for (int kt = 0; kt < 6; ++kt) {
                const int c0 = 16 * kt + 2 * tig;
                __half2 h;
                h = __floats2half2_rn(r0[c0],     r0[c0 + 1]);
                s.A[t2][kt][0] = *reinterpret_cast<uint32_t*>(&h);
                h = __floats2half2_rn(r1[c0],     r1[c0 + 1]);
                s.A[t2][kt][1] = *reinterpret_cast<uint32_t*>(&h);
                h = __floats2half2_rn(r0[c0 + 8], r0[c0 + 9]);
                s.A[t2][kt][2] = *reinterpret_cast<uint32_t*>(&h);
                h = __floats2half2_rn(r1[c0 + 8], r1[c0 + 9]);
                s.A[t2][kt][3] = *reinterpret_cast<uint32_t*>(&h);
            }
        }
    } else {
        s.fw0 = fc_w[lane]; s.fw1 = fc_w[lane + 32]; s.fw2 = fc_w[lane + 64];
        s.fcb = fc_b[0];
    }
    if (tid < HID) hb0[tid] = __float2half_rn(0.f);   // h0 = 0; c0 = 0 in regs
    __syncthreads();

    // 2x-unrolled: even step hb0->hb1, odd step hb1->hb0.
    #pragma unroll 1
    for (int t = 0; t < TSTEPS; t += 2) {
        lstm_step(t,     hb0, hb1, xs, out, s, w, lane, b);
        lstm_step(t + 1, hb1, hb0, xs, out, s, w, lane, b);
    }

    // Final output for t = TSTEPS-1 (odd step wrote into hb0).
    if (w == 12) {
        float p = s.fw0 * __half2float(hb0[lane])
                + s.fw1 * __half2float(hb0[lane + 32])
                + s.fw2 * __half2float(hb0[lane + 64]);
        #pragma unroll
        for (int off = 16; off > 0; off >>= 1)
            p += __shfl_xor_sync(0xffffffffu, p, off);
        if (lane == 0)
            out[(size_t)(TSTEPS - 1) * BATCH + b] = p + s.fcb + xs[TSTEPS - 1];
    }
}

extern "C" void kernel_launch(void* const* d_in, const int* in_sizes, int n_in,
                              void* d_out, int out_size)
{
    const float* x    = (const float*)d_in[0];
    const float* w_ih = (const float*)d_in[1];
    const float* w_hh = (const float*)d_in[2];
    const float* b_ih = (const float*)d_in[3];
    const float* b_hh = (const float*)d_in[4];
    const float* fc_w = (const float*)d_in[5];
    const float* fc_b = (const float*)d_in[6];
    float* out = (float*)d_out;

    cudaFuncSetAttribute(lstm_mma,
                         cudaFuncAttributeMaxDynamicSharedMemorySize,
                         (int)SMEM_BYTES);
    lstm_mma<<<BATCH, NTH, SMEM_BYTES>>>(x, w_ih, w_hh, b_ih, b_hh,
                                         fc_w, fc_b, out);
}